// round 8
// baseline (speedup 1.0000x reference)
#include <cuda_runtime.h>
#include <cuda_bf16.h>

// ---------------------------------------------------------------------------
// 18-qubit statevector fidelity |<psi2|psi1>|^2, hardware-efficient ansatz.
// R8: packed f32x2 with AMP-PAIR packing + SoA state.
// State stored as separate re/im planes. Each thread holds 4 amps as 2 packs:
// pack = (amp, amp^1) over amp bit 0; P_re=(a0.re,a1.re) u64, P_im likewise.
// All gates except q0 act on non-pack bits -> pure packed mul/fma f32x2
// (2x fewer FMA-pipe ops, zero pack/swap churn). q0 is within-pack (2 swaps).
//   passA: q0(within) q1(between) q2-6(shfl) | T | q7(between) q8,9(shfl)
//   passB: q10-14(shfl)                      | T | q15(between) q16,17(shfl)+CZ
// ---------------------------------------------------------------------------

#define NQ 18
#define NL 6
#define NSTATE (1 << NQ)

typedef unsigned long long u64;

__device__ float d_re[2][NSTATE];
__device__ float d_im[2][NSTATE];
// duplicated packed coeffs per (s,l,q): [m00x,m00y,m01x,m01y,m10x,m10y,m11x,m11y], each (v,v)
__device__ u64 d_dup[2][NL][NQ][8];
// mixed coeffs for q0 within-pack gate per (s,l): C1=(m00x,m11x) C2p=(m00y,m11y) C3=(m01x,m10x) C4p=(m01y,m10y)
__device__ u64 d_mix[2][NL][4];
__device__ double d_acc[2];

// ---- packed helpers -------------------------------------------------------
__device__ __forceinline__ u64 f2pack(float lo, float hi) {
    u64 r;
    asm("mov.b64 %0, {%1, %2};" : "=l"(r) : "f"(lo), "f"(hi));
    return r;
}
__device__ __forceinline__ void f2unpack(u64 a, float& lo, float& hi) {
    asm("mov.b64 {%0, %1}, %2;" : "=f"(lo), "=f"(hi) : "l"(a));
}
__device__ __forceinline__ u64 fma2(u64 a, u64 b, u64 c) {
    u64 d;
    asm("fma.rn.f32x2 %0, %1, %2, %3;" : "=l"(d) : "l"(a), "l"(b), "l"(c));
    return d;
}
__device__ __forceinline__ u64 mul2(u64 a, u64 b) {
    u64 d;
    asm("mul.rn.f32x2 %0, %1, %2;" : "=l"(d) : "l"(a), "l"(b));
    return d;
}
__device__ __forceinline__ u64 neg2(u64 a) { return a ^ 0x8000000080000000ull; }

__device__ __forceinline__ float2 cmulh(float2 a, float2 b) {
    return make_float2(a.x * b.x - a.y * b.y, a.x * b.y + a.y * b.x);
}
__device__ __forceinline__ float2 caddh(float2 a, float2 b) {
    return make_float2(a.x + b.x, a.y + b.y);
}
__device__ __forceinline__ float2 rscaleh(float r, float2 v) {
    return make_float2(r * v.x, r * v.y);
}

__global__ void qk_prep(const float* __restrict__ x1, const float* __restrict__ x2,
                        const float* __restrict__ iscale, const float* __restrict__ var) {
    int t = threadIdx.x;
    if (t < 2) d_acc[t] = 0.0;
    if (t >= 2 * NL * NQ) return;
    int s = t / (NL * NQ);
    int r = t % (NL * NQ);
    int l = r / NQ;
    int q = r % NQ;
    const float* x = s ? x2 : x1;

    float a = iscale[l * NQ + q] * x[q];
    float b = var[l * 2 * NQ + q];
    float c = var[l * 2 * NQ + NQ + q];

    float sa, ca, sb, cb, sc, cc;
    sincosf(0.5f * a, &sa, &ca);
    sincosf(0.5f * b, &sb, &cb);
    sincosf(0.5f * c, &sc, &cc);

    float2 X00 = make_float2(ca, 0.f), X01 = make_float2(0.f, -sa);
    float2 X10 = make_float2(0.f, -sa), X11 = make_float2(ca, 0.f);
    float2 M100 = caddh(rscaleh(cb, X00), rscaleh(-sb, X10));
    float2 M101 = caddh(rscaleh(cb, X01), rscaleh(-sb, X11));
    float2 M110 = caddh(rscaleh(sb, X00), rscaleh(cb, X10));
    float2 M111 = caddh(rscaleh(sb, X01), rscaleh(cb, X11));
    float2 e0 = make_float2(cc, -sc);
    float2 e1 = make_float2(cc, sc);
    float2 m00 = cmulh(e0, M100);
    float2 m01 = cmulh(e0, M101);
    float2 m10 = cmulh(e1, M110);
    float2 m11 = cmulh(e1, M111);

    u64* g = d_dup[s][l][q];
    g[0] = f2pack(m00.x, m00.x);
    g[1] = f2pack(m00.y, m00.y);
    g[2] = f2pack(m01.x, m01.x);
    g[3] = f2pack(m01.y, m01.y);
    g[4] = f2pack(m10.x, m10.x);
    g[5] = f2pack(m10.y, m10.y);
    g[6] = f2pack(m11.x, m11.x);
    g[7] = f2pack(m11.y, m11.y);
    if (q == 0) {
        d_mix[s][l][0] = f2pack(m00.x, m11.x);
        d_mix[s][l][1] = f2pack(m00.y, m11.y);
        d_mix[s][l][2] = f2pack(m01.x, m10.x);
        d_mix[s][l][3] = f2pack(m01.y, m10.y);
    }
}

// between-pack gate: A' = m00*A + m01*B ; B' = m10*A + m11*B (packed over 2 amps)
__device__ __forceinline__ void gate_between(u64& Are, u64& Aim, u64& Bre, u64& Bim,
                                             const u64* g) {
    u64 m00x = g[0], m00y = g[1], m01x = g[2], m01y = g[3];
    u64 m10x = g[4], m10y = g[5], m11x = g[6], m11y = g[7];
    u64 nAre = fma2(m01x, Bre, fma2(neg2(m01y), Bim, fma2(neg2(m00y), Aim, mul2(m00x, Are))));
    u64 nAim = fma2(m01x, Bim, fma2(m01y, Bre, fma2(m00y, Are, mul2(m00x, Aim))));
    u64 nBre = fma2(m11x, Bre, fma2(neg2(m11y), Bim, fma2(neg2(m10y), Aim, mul2(m10x, Are))));
    u64 nBim = fma2(m11x, Bim, fma2(m11y, Bre, fma2(m10y, Are, mul2(m10x, Aim))));
    Are = nAre; Aim = nAim; Bre = nBre; Bim = nBim;
}

// within-pack gate (q0): partners are the two slots of the pack
__device__ __forceinline__ void gate_within(u64& Pre, u64& Pim,
                                            u64 C1, u64 C2p, u64 C3, u64 C4p) {
    float rlo, rhi, ilo, ihi;
    f2unpack(Pre, rlo, rhi);
    f2unpack(Pim, ilo, ihi);
    u64 rsw = f2pack(rhi, rlo);
    u64 isw = f2pack(ihi, ilo);
    u64 nre = fma2(C3, rsw, fma2(neg2(C4p), isw, fma2(neg2(C2p), Pim, mul2(C1, Pre))));
    u64 nim = fma2(C3, isw, fma2(C4p, rsw, fma2(C2p, Pre, mul2(C1, Pim))));
    Pre = nre; Pim = nim;
}

// shfl gate on one pack; coefficients pre-selected per lane (duplicated)
__device__ __forceinline__ void gate_shflp(u64& vre, u64& vim, int mask,
                                           u64 cax, u64 cayp, u64 cbx, u64 cbyp) {
    u64 pre = __shfl_xor_sync(0xFFFFFFFFu, vre, mask);
    u64 pim = __shfl_xor_sync(0xFFFFFFFFu, vim, mask);
    u64 nre = fma2(cbx, pre, fma2(neg2(cbyp), pim, fma2(neg2(cayp), vim, mul2(cax, vre))));
    u64 nim = fma2(cbx, pim, fma2(cbyp, pre, fma2(cayp, vre, mul2(cax, vim))));
    vre = nre; vim = nim;
}

// smem swizzle over 9-bit u64-slot index: folds bit4->bit0, bit7->bit3.
// Conflict-free for STS phase (slots lane<<1|{0,1}) and LDS phase
// (slots (lane&7) | lanebit3<<7), w constant within a warp.
__device__ __forceinline__ unsigned swz(unsigned x) {
    return x ^ ((x >> 4) & 9u);
}

#define SHFL_GATE2(j, mask, Are, Aim, Bre, Bim)                               \
    {                                                                         \
        const u64* gq = sG + 8 * (j);                                         \
        bool hi = (lane & (mask)) != 0;                                       \
        u64 cax = hi ? gq[6] : gq[0];                                         \
        u64 cayp = hi ? gq[7] : gq[1];                                        \
        u64 cbx = hi ? gq[4] : gq[2];                                         \
        u64 cbyp = hi ? gq[5] : gq[3];                                        \
        gate_shflp(Are, Aim, (mask), cax, cayp, cbx, cbyp);                   \
        gate_shflp(Bre, Bim, (mask), cax, cayp, cbx, cbyp);                   \
    }

// ---------------------------------------------------------------------------
// passA: qubits 0..9. Local 10-bit amp window = global bits 0-9; blk -> 10-17.
// mapping1: amp = k | lane<<2 | w<<7 (k in 0..3); packs over bit 0.
// transpose in u64-slot space (slot = amp>>1):
// mapping2 slots: s2 = (lane&7) | w<<3 | lanebit3<<7 | lanebit4<<8; k' = slot bit 6 (amp bit 7).
// gates mapping2: q7 between-pack (slot bit6), q8 shfl mask 8, q9 shfl mask 16.
// ---------------------------------------------------------------------------
__global__ void __launch_bounds__(256) qk_passA(int layer, int init) {
    __shared__ u64 smre[512];
    __shared__ u64 smim[512];
    __shared__ u64 sG[84];
    int tid = threadIdx.x;
    int lane = tid & 31;
    int w = tid >> 5;
    int blk = blockIdx.x;
    int s = blk >> 8;
    unsigned blkbase = ((unsigned)(blk & 255)) << 10;
    float* re = d_re[s];
    float* im = d_im[s];

    if (tid < 80) sG[tid] = (&d_dup[s][layer][0][0])[tid];
    else if (tid < 84) sG[tid] = d_mix[s][layer][tid - 80];

    unsigned l1 = ((unsigned)lane << 2) | ((unsigned)w << 7);
    u64 P0re, P0im, P1re, P1im;

    if (init) {
        P0re = P0im = P1re = P1im = 0ull;
        if ((blkbase | l1) == 0) P0re = f2pack(1.f, 0.f);
    } else {
        ulonglong2 r2 = *(const ulonglong2*)(re + blkbase + l1);
        ulonglong2 i2 = *(const ulonglong2*)(im + blkbase + l1);
        P0re = r2.x; P1re = r2.y;
        P0im = i2.x; P1im = i2.y;
    }
    __syncthreads();                                // sG ready

    // q0: within-pack
    gate_within(P0re, P0im, sG[80], sG[81], sG[82], sG[83]);
    gate_within(P1re, P1im, sG[80], sG[81], sG[82], sG[83]);
    // q1: between packs (amp bit 1)
    gate_between(P0re, P0im, P1re, P1im, sG + 8);
    // q2..q6: shfl (lane bits 0-4)
    SHFL_GATE2(2, 1, P0re, P0im, P1re, P1im)
    SHFL_GATE2(3, 2, P0re, P0im, P1re, P1im)
    SHFL_GATE2(4, 4, P0re, P0im, P1re, P1im)
    SHFL_GATE2(5, 8, P0re, P0im, P1re, P1im)
    SHFL_GATE2(6, 16, P0re, P0im, P1re, P1im)

    // transpose: slot = amp>>1
    unsigned s1 = l1 >> 1;                          // lane<<1 | w<<6
    smre[swz(s1)] = P0re;
    smre[swz(s1 | 1u)] = P1re;
    smim[swz(s1)] = P0im;
    smim[swz(s1 | 1u)] = P1im;
    __syncthreads();

    unsigned s2 = ((unsigned)lane & 7u) | ((unsigned)w << 3)
                | (((unsigned)lane >> 3) & 1u) << 7 | ((unsigned)lane >> 4) << 8;
    u64 Q0re = smre[swz(s2)], Q0im = smim[swz(s2)];
    u64 Q1re = smre[swz(s2 | 64u)], Q1im = smim[swz(s2 | 64u)];

    // q7: between packs (amp bit 7 = slot bit 6)
    gate_between(Q0re, Q0im, Q1re, Q1im, sG + 56);
    // q8: shfl lane bit 3; q9: shfl lane bit 4
    SHFL_GATE2(8, 8, Q0re, Q0im, Q1re, Q1im)
    SHFL_GATE2(9, 16, Q0re, Q0im, Q1re, Q1im)

    unsigned base2 = s2 << 1;
    *(u64*)(re + blkbase + base2) = Q0re;
    *(u64*)(im + blkbase + base2) = Q0im;
    *(u64*)(re + blkbase + base2 + 128u) = Q1re;
    *(u64*)(im + blkbase + base2 + 128u) = Q1im;
}

// ---------------------------------------------------------------------------
// passB: qubits 10..17 + CZ sign. Local bits 0,1 -> global 0,1 (ungated,
// ride along for coalescing/packing); local 2-9 -> global 10-17; blk -> 2-9.
// g(amp) = (amp&3) | rest<<2 | (amp>>2)<<10
// ---------------------------------------------------------------------------
__global__ void __launch_bounds__(256) qk_passB(int layer) {
    __shared__ u64 smre[512];
    __shared__ u64 smim[512];
    __shared__ u64 sG[64];
    int tid = threadIdx.x;
    int lane = tid & 31;
    int w = tid >> 5;
    int blk = blockIdx.x;
    int s = blk >> 8;
    unsigned rest = (unsigned)(blk & 255);
    float* re = d_re[s];
    float* im = d_im[s];

    if (tid < 64) sG[tid] = (&d_dup[s][layer][10][0])[tid];

    unsigned l1 = ((unsigned)lane << 2) | ((unsigned)w << 7);
    unsigned g1 = (rest << 2) | ((l1 >> 2) << 10);  // l1&3 == 0

    ulonglong2 r2 = *(const ulonglong2*)(re + g1);
    ulonglong2 i2 = *(const ulonglong2*)(im + g1);
    u64 P0re = r2.x, P1re = r2.y, P0im = i2.x, P1im = i2.y;
    __syncthreads();                                // sG ready

    // q10..q14: shfl (lane bits 0-4); j = q-10
    SHFL_GATE2(0, 1, P0re, P0im, P1re, P1im)
    SHFL_GATE2(1, 2, P0re, P0im, P1re, P1im)
    SHFL_GATE2(2, 4, P0re, P0im, P1re, P1im)
    SHFL_GATE2(3, 8, P0re, P0im, P1re, P1im)
    SHFL_GATE2(4, 16, P0re, P0im, P1re, P1im)

    unsigned s1 = l1 >> 1;
    smre[swz(s1)] = P0re;
    smre[swz(s1 | 1u)] = P1re;
    smim[swz(s1)] = P0im;
    smim[swz(s1 | 1u)] = P1im;
    __syncthreads();

    unsigned s2 = ((unsigned)lane & 7u) | ((unsigned)w << 3)
                | (((unsigned)lane >> 3) & 1u) << 7 | ((unsigned)lane >> 4) << 8;
    u64 Q0re = smre[swz(s2)], Q0im = smim[swz(s2)];
    u64 Q1re = smre[swz(s2 | 64u)], Q1im = smim[swz(s2 | 64u)];

    // q15: between packs (amp bit 7); j = 5
    gate_between(Q0re, Q0im, Q1re, Q1im, sG + 40);
    // q16: shfl lane bit 3 (j=6); q17: shfl lane bit 4 (j=7)
    SHFL_GATE2(6, 8, Q0re, Q0im, Q1re, Q1im)
    SHFL_GATE2(7, 16, Q0re, Q0im, Q1re, Q1im)

    // CZ chain sign + SoA store
    unsigned base2 = s2 << 1;
    unsigned g2a = (base2 & 3u) | (rest << 2) | ((base2 >> 2) << 10);
    unsigned base2b = base2 | 128u;
    unsigned g2b = (base2b & 3u) | (rest << 2) | ((base2b >> 2) << 10);

    {
        unsigned p0 = __popc(g2a & (g2a >> 1) & 0x1FFFFu) & 1u;
        unsigned gb = g2a | 1u;
        unsigned p1 = __popc(gb & (gb >> 1) & 0x1FFFFu) & 1u;
        u64 m = ((u64)(p0 << 31)) | (((u64)(p1 << 31)) << 32);
        Q0re ^= m;
        Q0im ^= m;
    }
    {
        unsigned p0 = __popc(g2b & (g2b >> 1) & 0x1FFFFu) & 1u;
        unsigned gb = g2b | 1u;
        unsigned p1 = __popc(gb & (gb >> 1) & 0x1FFFFu) & 1u;
        u64 m = ((u64)(p0 << 31)) | (((u64)(p1 << 31)) << 32);
        Q1re ^= m;
        Q1im ^= m;
    }

    *(u64*)(re + g2a) = Q0re;
    *(u64*)(im + g2a) = Q0im;
    *(u64*)(re + g2b) = Q1re;
    *(u64*)(im + g2b) = Q1im;
}

// ---------------------------------------------------------------------------
// Overlap reduction (SoA): acc += conj(psi2) . psi1
// ---------------------------------------------------------------------------
__global__ void qk_reduce() {
    int t = blockIdx.x * blockDim.x + threadIdx.x;
    int nthreads = gridDim.x * blockDim.x;
    double re = 0.0, im = 0.0;
    for (int i = t; i < NSTATE; i += nthreads) {
        float ar = d_re[0][i], ai = d_im[0][i];
        float br = d_re[1][i], bi = d_im[1][i];
        re += (double)br * ar + (double)bi * ai;
        im += (double)br * ai - (double)bi * ar;
    }
#pragma unroll
    for (int o = 16; o > 0; o >>= 1) {
        re += __shfl_down_sync(0xFFFFFFFFu, re, o);
        im += __shfl_down_sync(0xFFFFFFFFu, im, o);
    }
    if ((threadIdx.x & 31) == 0) {
        atomicAdd(&d_acc[0], re);
        atomicAdd(&d_acc[1], im);
    }
}

__global__ void qk_final(float* out) {
    double re = d_acc[0], im = d_acc[1];
    out[0] = (float)(re * re + im * im);
}

extern "C" void kernel_launch(void* const* d_in, const int* in_sizes, int n_in,
                              void* d_out, int out_size) {
    const float* x1 = (const float*)d_in[0];
    const float* x2 = (const float*)d_in[1];
    const float* iscale = (const float*)d_in[2];
    const float* var = (const float*)d_in[3];

    qk_prep<<<1, 256>>>(x1, x2, iscale, var);
    for (int l = 0; l < NL; l++) {
        qk_passA<<<512, 256>>>(l, l == 0 ? 1 : 0);
        qk_passB<<<512, 256>>>(l);
    }
    qk_reduce<<<148, 256>>>();
    qk_final<<<1, 1>>>((float*)d_out);
}

// round 9
// speedup vs baseline: 1.1680x; 1.1680x over previous
#include <cuda_runtime.h>
#include <cuda_bf16.h>

// ---------------------------------------------------------------------------
// 18-qubit statevector fidelity |<psi2|psi1>|^2, hardware-efficient ansatz.
// R9: 8 amps/thread, 3 register-gate mappings per pass, 2 smem transposes.
// passA gates q0-q8 with ZERO shuffles; passB gates q9-q17 (one shfl for q17)
// + CZ sign. SHFL count per amp drops 12 -> 1; FFMA total unchanged.
// Swizzles (u64/float2 slot space, 10-bit local index):
//   swzA = l ^ ((l>>3)&15) ^ ((l>>6)&6)   (transpose 1: m1-write / m2-read)
//   swzB = l ^ ((l>>5)&14)                (transpose 2: m2-write / m3-read)
// both verified bijective per half-warp phase for their access patterns.
// ---------------------------------------------------------------------------

#define NQ 18
#define NL 6
#define NSTATE (1 << NQ)

__device__ float2 d_psi[2][NSTATE];
// per (s,l,q): f4[0]=(m00.x,m00.y,m01.x,m01.y), f4[1]=(m10.x,m10.y,m11.x,m11.y)
__device__ float4 d_mats[2][NL][NQ][2];
__device__ double d_acc[2];

__device__ __forceinline__ float2 cmulh(float2 a, float2 b) {
    return make_float2(a.x * b.x - a.y * b.y, a.x * b.y + a.y * b.x);
}
__device__ __forceinline__ float2 caddh(float2 a, float2 b) {
    return make_float2(a.x + b.x, a.y + b.y);
}
__device__ __forceinline__ float2 rscaleh(float r, float2 v) {
    return make_float2(r * v.x, r * v.y);
}

__global__ void qk_prep(const float* __restrict__ x1, const float* __restrict__ x2,
                        const float* __restrict__ iscale, const float* __restrict__ var) {
    int t = threadIdx.x;
    if (t < 2) d_acc[t] = 0.0;
    if (t >= 2 * NL * NQ) return;
    int s = t / (NL * NQ);
    int r = t % (NL * NQ);
    int l = r / NQ;
    int q = r % NQ;
    const float* x = s ? x2 : x1;

    float a = iscale[l * NQ + q] * x[q];
    float b = var[l * 2 * NQ + q];
    float c = var[l * 2 * NQ + NQ + q];

    float sa, ca, sb, cb, sc, cc;
    sincosf(0.5f * a, &sa, &ca);
    sincosf(0.5f * b, &sb, &cb);
    sincosf(0.5f * c, &sc, &cc);

    float2 X00 = make_float2(ca, 0.f), X01 = make_float2(0.f, -sa);
    float2 X10 = make_float2(0.f, -sa), X11 = make_float2(ca, 0.f);
    float2 M100 = caddh(rscaleh(cb, X00), rscaleh(-sb, X10));
    float2 M101 = caddh(rscaleh(cb, X01), rscaleh(-sb, X11));
    float2 M110 = caddh(rscaleh(sb, X00), rscaleh(cb, X10));
    float2 M111 = caddh(rscaleh(sb, X01), rscaleh(cb, X11));
    float2 e0 = make_float2(cc, -sc);
    float2 e1 = make_float2(cc, sc);
    float2 m00 = cmulh(e0, M100);
    float2 m01 = cmulh(e0, M101);
    float2 m10 = cmulh(e1, M110);
    float2 m11 = cmulh(e1, M111);

    d_mats[s][l][q][0] = make_float4(m00.x, m00.y, m01.x, m01.y);
    d_mats[s][l][q][1] = make_float4(m10.x, m10.y, m11.x, m11.y);
}

__device__ __forceinline__ void gate_pair(float2& a, float2& b, float4 c0, float4 c1) {
    float nax = fmaf(c0.z, b.x, fmaf(-c0.w, b.y, fmaf(c0.x, a.x, -c0.y * a.y)));
    float nay = fmaf(c0.z, b.y, fmaf(c0.w, b.x, fmaf(c0.x, a.y, c0.y * a.x)));
    float nbx = fmaf(c1.z, b.x, fmaf(-c1.w, b.y, fmaf(c1.x, a.x, -c1.y * a.y)));
    float nby = fmaf(c1.z, b.y, fmaf(c1.w, b.x, fmaf(c1.x, a.y, c1.y * a.x)));
    a = make_float2(nax, nay);
    b = make_float2(nbx, nby);
}

__device__ __forceinline__ float2 gate_shfl(float2 v, int mask,
                                            float cax, float cay, float cbx, float cby) {
    float px = __shfl_xor_sync(0xFFFFFFFFu, v.x, mask);
    float py = __shfl_xor_sync(0xFFFFFFFFu, v.y, mask);
    float rx = fmaf(cbx, px, fmaf(-cby, py, fmaf(cax, v.x, -cay * v.y)));
    float ry = fmaf(cbx, py, fmaf(cby, px, fmaf(cax, v.y, cay * v.x)));
    return make_float2(rx, ry);
}

__device__ __forceinline__ unsigned swzA(unsigned l) {
    return l ^ ((l >> 3) & 15u) ^ ((l >> 6) & 6u);
}
__device__ __forceinline__ unsigned swzB(unsigned l) {
    return l ^ ((l >> 5) & 14u);
}

// 3 reg gates over v[8]: qubit at v-index bit0 (stride 1), bit1, bit2
#define GATES3(j0, j1, j2)                                                    \
    {                                                                         \
        float4 c0 = sMat[2 * (j0)], c1 = sMat[2 * (j0) + 1];                  \
        gate_pair(v[0], v[1], c0, c1);                                        \
        gate_pair(v[2], v[3], c0, c1);                                        \
        gate_pair(v[4], v[5], c0, c1);                                        \
        gate_pair(v[6], v[7], c0, c1);                                        \
    }                                                                         \
    {                                                                         \
        float4 c0 = sMat[2 * (j1)], c1 = sMat[2 * (j1) + 1];                  \
        gate_pair(v[0], v[2], c0, c1);                                        \
        gate_pair(v[1], v[3], c0, c1);                                        \
        gate_pair(v[4], v[6], c0, c1);                                        \
        gate_pair(v[5], v[7], c0, c1);                                        \
    }                                                                         \
    {                                                                         \
        float4 c0 = sMat[2 * (j2)], c1 = sMat[2 * (j2) + 1];                  \
        gate_pair(v[0], v[4], c0, c1);                                        \
        gate_pair(v[1], v[5], c0, c1);                                        \
        gate_pair(v[2], v[6], c0, c1);                                        \
        gate_pair(v[3], v[7], c0, c1);                                        \
    }

// ---------------------------------------------------------------------------
// passA: qubits 0..8 (all reg gates). 512 blocks x 128 thr, 8 amps/thread.
// Local 10-bit amp window == global bits 0-9 (bit 9 ungated rider).
// m1: l = k | lane<<3 | w<<8          -> gates q0,q1,q2
// m2: l = (lane&1) | w<<1 | k<<3 | ((lane>>1)&15)<<6  -> gates q3,q4,q5
// m3: l = (lane&15) | w<<4 | k<<6 | (lane>>4)<<9      -> gates q6,q7,q8
// ---------------------------------------------------------------------------
__global__ void __launch_bounds__(128) qk_passA(int layer, int init) {
    __shared__ float2 sm[1024];
    __shared__ float4 sMat[18];
    int tid = threadIdx.x;
    int lane = tid & 31;
    unsigned w = (unsigned)(tid >> 5);              // 0..3
    int blk = blockIdx.x;
    int s = blk >> 8;
    unsigned blkbase = ((unsigned)(blk & 255)) << 10;
    float2* psi = d_psi[s];

    if (tid < 18) sMat[tid] = (&d_mats[s][layer][0][0])[tid];

    unsigned l1 = ((unsigned)lane << 3) | (w << 8);
    float2 v[8];

    if (init) {
#pragma unroll
        for (int k = 0; k < 8; k++) v[k] = make_float2(0.f, 0.f);
        if ((blkbase | l1) == 0) v[0] = make_float2(1.f, 0.f);
    } else {
        const float4* p4 = (const float4*)(psi + blkbase + l1);
#pragma unroll
        for (int j = 0; j < 4; j++) {
            float4 t4 = p4[j];
            v[2 * j] = make_float2(t4.x, t4.y);
            v[2 * j + 1] = make_float2(t4.z, t4.w);
        }
    }
    __syncthreads();                                // sMat ready

    GATES3(0, 1, 2)                                 // q0,q1,q2

    // T1
#pragma unroll
    for (int k = 0; k < 8; k++) sm[swzA(l1 | (unsigned)k)] = v[k];
    __syncthreads();

    unsigned l2 = ((unsigned)lane & 1u) | (w << 1) | ((((unsigned)lane >> 1) & 15u) << 6);
#pragma unroll
    for (int k = 0; k < 8; k++) v[k] = sm[swzA(l2 | ((unsigned)k << 3))];

    GATES3(3, 4, 5)                                 // q3,q4,q5
    __syncthreads();                                // all T1 reads done

    // T2
#pragma unroll
    for (int k = 0; k < 8; k++) sm[swzB(l2 | ((unsigned)k << 3))] = v[k];
    __syncthreads();

    unsigned l3 = ((unsigned)lane & 15u) | (w << 4) | (((unsigned)lane >> 4) << 9);
#pragma unroll
    for (int k = 0; k < 8; k++) v[k] = sm[swzB(l3 | ((unsigned)k << 6))];

    GATES3(6, 7, 8)                                 // q6,q7,q8

    // store: per k, 16 lanes = 128B contiguous (x2 for lane bit4)
#pragma unroll
    for (int k = 0; k < 8; k++)
        psi[blkbase + l3 + ((unsigned)k << 6)] = v[k];
}

// ---------------------------------------------------------------------------
// passB: qubits 9..17 + CZ. Local bit 0 -> global 0 (rider); local 1-9 ->
// global 9-17; rest (blk&255) -> global 1-8.  g(l) = (l&1) | rest<<1 | (l>>1)<<9
// m1: k bits {0(rider),1,2} -> gates q9 (stride 2), q10 (stride 4)
// m2: k bits {3,4,5} -> q11,q12,q13
// m3: k bits {6,7,8} -> q14,q15,q16; q17 = local bit 9 = lane bit 4 (shfl)
// ---------------------------------------------------------------------------
__global__ void __launch_bounds__(128) qk_passB(int layer) {
    __shared__ float2 sm[1024];
    __shared__ float4 sMat[18];
    int tid = threadIdx.x;
    int lane = tid & 31;
    unsigned w = (unsigned)(tid >> 5);
    int blk = blockIdx.x;
    int s = blk >> 8;
    unsigned rest = (unsigned)(blk & 255);
    float2* psi = d_psi[s];

    if (tid < 18) sMat[tid] = (&d_mats[s][layer][9][0])[tid];

    unsigned l1 = ((unsigned)lane << 3) | (w << 8);
    float2 v[8];

    // load: amps (g, g+1) per float4; f4 index = rest | ((l1>>1)+kk)<<8
    {
        const float4* p4 = (const float4*)psi;
#pragma unroll
        for (int kk = 0; kk < 4; kk++) {
            float4 t4 = p4[rest | (((l1 >> 1) + (unsigned)kk) << 8)];
            v[2 * kk] = make_float2(t4.x, t4.y);
            v[2 * kk + 1] = make_float2(t4.z, t4.w);
        }
    }
    __syncthreads();                                // sMat ready

    // m1: q9 (v-bit 1), q10 (v-bit 2); v-bit 0 is the global-bit-0 rider
    {
        float4 c0 = sMat[0], c1 = sMat[1];          // q9
        gate_pair(v[0], v[2], c0, c1);
        gate_pair(v[1], v[3], c0, c1);
        gate_pair(v[4], v[6], c0, c1);
        gate_pair(v[5], v[7], c0, c1);
    }
    {
        float4 c0 = sMat[2], c1 = sMat[3];          // q10
        gate_pair(v[0], v[4], c0, c1);
        gate_pair(v[1], v[5], c0, c1);
        gate_pair(v[2], v[6], c0, c1);
        gate_pair(v[3], v[7], c0, c1);
    }

    // T1
#pragma unroll
    for (int k = 0; k < 8; k++) sm[swzA(l1 | (unsigned)k)] = v[k];
    __syncthreads();

    unsigned l2 = ((unsigned)lane & 1u) | (w << 1) | ((((unsigned)lane >> 1) & 15u) << 6);
#pragma unroll
    for (int k = 0; k < 8; k++) v[k] = sm[swzA(l2 | ((unsigned)k << 3))];

    GATES3(2, 3, 4)                                 // q11,q12,q13
    __syncthreads();

    // T2
#pragma unroll
    for (int k = 0; k < 8; k++) sm[swzB(l2 | ((unsigned)k << 3))] = v[k];
    __syncthreads();

    unsigned l3 = ((unsigned)lane & 15u) | (w << 4) | (((unsigned)lane >> 4) << 9);
#pragma unroll
    for (int k = 0; k < 8; k++) v[k] = sm[swzB(l3 | ((unsigned)k << 6))];

    GATES3(5, 6, 7)                                 // q14,q15,q16

    // q17: local bit 9 = lane bit 4 -> shfl gate
    {
        float4 c0 = sMat[16], c1 = sMat[17];
        bool hi = (lane & 16) != 0;
        float cax = hi ? c1.z : c0.x;
        float cay = hi ? c1.w : c0.y;
        float cbx = hi ? c1.x : c0.z;
        float cby = hi ? c1.y : c0.w;
#pragma unroll
        for (int k = 0; k < 8; k++) v[k] = gate_shfl(v[k], 16, cax, cay, cbx, cby);
    }

    // CZ chain sign + store
#pragma unroll
    for (int k = 0; k < 8; k++) {
        unsigned l = l3 | ((unsigned)k << 6);
        unsigned g = (l & 1u) | (rest << 1) | ((l >> 1) << 9);
        unsigned tm = g & (g >> 1) & 0x1FFFFu;
        if (__popc(tm) & 1) {
            v[k].x = -v[k].x;
            v[k].y = -v[k].y;
        }
        psi[g] = v[k];
    }
}

__global__ void qk_reduce() {
    int t = blockIdx.x * blockDim.x + threadIdx.x;
    int nthreads = gridDim.x * blockDim.x;
    double re = 0.0, im = 0.0;
    for (int i = t; i < NSTATE; i += nthreads) {
        float2 a = d_psi[0][i];
        float2 b = d_psi[1][i];
        re += (double)b.x * a.x + (double)b.y * a.y;
        im += (double)b.x * a.y - (double)b.y * a.x;
    }
#pragma unroll
    for (int o = 16; o > 0; o >>= 1) {
        re += __shfl_down_sync(0xFFFFFFFFu, re, o);
        im += __shfl_down_sync(0xFFFFFFFFu, im, o);
    }
    if ((threadIdx.x & 31) == 0) {
        atomicAdd(&d_acc[0], re);
        atomicAdd(&d_acc[1], im);
    }
}

__global__ void qk_final(float* out) {
    double re = d_acc[0], im = d_acc[1];
    out[0] = (float)(re * re + im * im);
}

extern "C" void kernel_launch(void* const* d_in, const int* in_sizes, int n_in,
                              void* d_out, int out_size) {
    const float* x1 = (const float*)d_in[0];
    const float* x2 = (const float*)d_in[1];
    const float* iscale = (const float*)d_in[2];
    const float* var = (const float*)d_in[3];

    qk_prep<<<1, 256>>>(x1, x2, iscale, var);
    for (int l = 0; l < NL; l++) {
        qk_passA<<<512, 128>>>(l, l == 0 ? 1 : 0);
        qk_passB<<<512, 128>>>(l);
    }
    qk_reduce<<<148, 256>>>();
    qk_final<<<1, 1>>>((float*)d_out);
}